// round 17
// baseline (speedup 1.0000x reference)
#include <cuda_runtime.h>
#include <cuda_fp16.h>
#include <cstdint>

// ---------------------------------------------------------------------------
// GCN: out = softmax(relu(agg(relu(agg(relu(agg(X@W1))@W2))@W3)))
// agg(X) @ W == agg(X @ W)  -> GEMM first (mma.sync m16n8k16 fp16, fp32 acc),
// then CSR SpMM. dinv factored into GEMM/agg epilogues. CSR = col only.
// count_deg emits per-edge rank (atomicAdd return) -> scatter is atomic-free.
// g_deg self-restores to zero (scatter stores 0). 10 launches.
// ---------------------------------------------------------------------------

#define NMAX 50000
#define EMAX 800000

__device__ int    g_is64;
__device__ int    g_deg[NMAX];        // zero-init; scatter restores zeros
__device__ int    g_rank[EMAX];       // per-edge slot within its dst row
__device__ int    g_rowstart[NMAX + 1];
__device__ int    g_col[EMAX];
__device__ float  g_dinv[NMAX];
__device__ __half g_bufY[(size_t)NMAX * 128];   // GEMM out (fp16, pre-scaled)
__device__ __half g_bufH[(size_t)NMAX * 128];   // agg out (fp16, GEMM A side)
__device__ uint2 g_wt1[32 * 128];
__device__ uint2 g_wt2[32 * 128];
__device__ uint2 g_wt3[32 * 64];

__device__ __forceinline__ uint32_t f2h2(float x, float y) {
    __half2 h = __floats2half2_rn(x, y);
    return *(uint32_t*)&h;
}

__device__ __forceinline__ void mma_f16(float* d, uint32_t a0, uint32_t a1,
                                        uint32_t a2, uint32_t a3,
                                        uint32_t b0, uint32_t b1) {
    asm volatile(
        "mma.sync.aligned.m16n8k16.row.col.f32.f16.f16.f32 "
        "{%0,%1,%2,%3}, {%4,%5,%6,%7}, {%8,%9}, {%0,%1,%2,%3};"
        : "+f"(d[0]), "+f"(d[1]), "+f"(d[2]), "+f"(d[3])
        : "r"(a0), "r"(a1), "r"(a2), "r"(a3), "r"(b0), "r"(b1));
}

__device__ __forceinline__ void acc8(float* acc, uint4 r) {
    float2 v;
    v = __half22float2(*(__half2*)&r.x); acc[0] += v.x; acc[1] += v.y;
    v = __half22float2(*(__half2*)&r.y); acc[2] += v.x; acc[3] += v.y;
    v = __half22float2(*(__half2*)&r.z); acc[4] += v.x; acc[5] += v.y;
    v = __half22float2(*(__half2*)&r.w); acc[6] += v.x; acc[7] += v.y;
}

__device__ __forceinline__ int edge_at(const void* ei, int E, int half, int e) {
    if (g_is64) return (int)((const long long*)ei)[(size_t)half * E + e];
    return ((const int*)ei)[(size_t)half * E + e];
}

// ---------------------------------------------------------------- W prep (+probe)
__device__ __forceinline__ uint2* wtPtr(int w) {
    return w == 1 ? g_wt1 : (w == 2 ? g_wt2 : g_wt3);
}
__device__ __forceinline__ void prep_one(const float* __restrict__ W,
                                         uint2* __restrict__ wt, int i, int NDIM) {
    int j = i / NDIM;
    int n = i % NDIM;
    int s = j >> 2;
    int tig = j & 3;
    int k0 = 16 * s + 2 * tig;
    uint2 v;
    v.x = f2h2(W[(size_t)k0 * NDIM + n], W[(size_t)(k0 + 1) * NDIM + n]);
    v.y = f2h2(W[(size_t)(k0 + 8) * NDIM + n], W[(size_t)(k0 + 9) * NDIM + n]);
    wt[i] = v;
}
__global__ void prep_all_kernel(const float* __restrict__ W1,
                                const float* __restrict__ W2,
                                const float* __restrict__ W3,
                                const void* __restrict__ ei, int E, int N) {
    if (blockIdx.x == 0) {
        __shared__ int allok;
        if (threadIdx.x == 0) allok = 1;
        __syncthreads();
        const long long* p = (const long long*)ei;
        int stride = E / 256;
        long long v = p[(size_t)threadIdx.x * stride];
        if (v < 0 || v >= (long long)N) atomicAnd(&allok, 0);
        __syncthreads();
        if (threadIdx.x == 0) g_is64 = allok;
    }
    int i = blockIdx.x * blockDim.x + threadIdx.x;  // 0..10239
    if (i < 4096) prep_one(W1, g_wt1, i, 128);
    else if (i < 8192) prep_one(W2, g_wt2, i - 4096, 128);
    else if (i < 10240) prep_one(W3, g_wt3, i - 8192, 64);
}

// ---------------------------------------------------------------- CSR build
// count also records each edge's arrival rank -> scatter needs no atomic
__global__ void count_deg_kernel(const void* __restrict__ ei, int E) {
    int e = blockIdx.x * blockDim.x + threadIdx.x;
    if (e < E) g_rank[e] = atomicAdd(&g_deg[edge_at(ei, E, 1, e)], 1);
}
__global__ __launch_bounds__(1024) void scan_kernel(int n) {
    const int tid = threadIdx.x;
    const int lane = tid & 31;
    const int wid = tid >> 5;
    const int C = (n + 1023) / 1024;
    const int base = tid * C;

    int sum = 0;
    for (int i = 0; i < C; i++) {
        int idx = base + i;
        if (idx < n) sum += g_deg[idx];
    }
    int inc = sum;
    #pragma unroll
    for (int off = 1; off < 32; off <<= 1) {
        int t = __shfl_up_sync(0xffffffffu, inc, off);
        if (lane >= off) inc += t;
    }
    __shared__ int ws[32];
    if (lane == 31) ws[wid] = inc;
    __syncthreads();
    if (wid == 0) {
        int v = ws[lane];
        #pragma unroll
        for (int off = 1; off < 32; off <<= 1) {
            int t = __shfl_up_sync(0xffffffffu, v, off);
            if (lane >= off) v += t;
        }
        ws[lane] = v;
    }
    __syncthreads();
    int warpoff = (wid == 0) ? 0 : ws[wid - 1];
    int run = warpoff + (inc - sum);
    if (tid == 0) g_rowstart[0] = 0;
    for (int i = 0; i < C; i++) {
        int idx = base + i;
        if (idx < n) {
            run += g_deg[idx];
            g_rowstart[idx + 1] = run;
        }
    }
}
// atomic-free scatter; restores g_deg to zero for the next graph replay
__global__ void scatter_kernel(const void* __restrict__ ei, int E) {
    int e = blockIdx.x * blockDim.x + threadIdx.x;
    if (e >= E) return;
    int s = edge_at(ei, E, 0, e);
    int d = edge_at(ei, E, 1, e);
    g_col[g_rowstart[d] + g_rank[e]] = s;
    g_deg[d] = 0;   // benign race: everyone writes 0
}

// ---------------------------------------------------------------- mma GEMM
template <int N_DIM, int WSEL, bool EXT>
__global__ __launch_bounds__(256) void gemm_mma(const float* __restrict__ Aext, int M) {
    extern __shared__ uint2 Bs[];
    __shared__ float sdinv[128];
    constexpr int NT = N_DIM / 8;
    constexpr int NPAD = N_DIM + 4;

    const int tid = threadIdx.x;
    const int blockRow = blockIdx.x * 128;
    const uint2* wt = wtPtr(WSEL);
    #pragma unroll
    for (int l = 0; l < (32 * N_DIM) / 256; l++) {
        int i = tid + l * 256;
        int j = i / N_DIM;
        int n = i % N_DIM;
        Bs[j * NPAD + n] = wt[i];
    }
    if (EXT && tid < 128) {
        int gr = blockRow + tid;
        int d = (gr < M) ? g_deg[gr] : 1;
        float dv = rsqrtf((float)(d > 0 ? d : 1));
        sdinv[tid] = dv;
        if (gr < M) g_dinv[gr] = dv;
    }
    __syncthreads();

    const int wid = tid >> 5;
    const int lane = tid & 31;
    const int g = lane >> 2;
    const int tig = lane & 3;
    const int rowBase = blockRow + wid * 16;
    const int m0 = rowBase + g;
    const int m1 = m0 + 8;
    const int r0 = m0 < M ? m0 : M - 1;
    const int r1 = m1 < M ? m1 : M - 1;

    float acc[NT][4];
    #pragma unroll
    for (int nt = 0; nt < NT; nt++) {
        acc[nt][0] = 0.f; acc[nt][1] = 0.f; acc[nt][2] = 0.f; acc[nt][3] = 0.f;
    }

    const float* Af0 = Aext + (size_t)r0 * 128;
    const float* Af1 = Aext + (size_t)r1 * 128;
    const __half* Ah0 = g_bufH + (size_t)r0 * 128;
    const __half* Ah1 = g_bufH + (size_t)r1 * 128;

    #pragma unroll
    for (int s = 0; s < 8; s++) {
        const int k0 = 16 * s + 2 * tig;
        uint32_t a0, a1, a2, a3;
        if (EXT) {
            float2 f;
            f = *(const float2*)(Af0 + k0);     a0 = f2h2(f.x, f.y);
            f = *(const float2*)(Af1 + k0);     a1 = f2h2(f.x, f.y);
            f = *(const float2*)(Af0 + k0 + 8); a2 = f2h2(f.x, f.y);
            f = *(const float2*)(Af1 + k0 + 8); a3 = f2h2(f.x, f.y);
        } else {
            a0 = *(const uint32_t*)(Ah0 + k0);
            a1 = *(const uint32_t*)(Ah1 + k0);
            a2 = *(const uint32_t*)(Ah0 + k0 + 8);
            a3 = *(const uint32_t*)(Ah1 + k0 + 8);
        }
        const uint2* brow = Bs + (size_t)(s * 4 + tig) * NPAD + g;
        #pragma unroll
        for (int nt = 0; nt < NT; nt++) {
            uint2 b = brow[nt * 8];
            mma_f16(acc[nt], a0, a1, a2, a3, b.x, b.y);
        }
    }

    const float dv0 = EXT ? sdinv[wid * 16 + g] : g_dinv[r0];
    const float dv1 = EXT ? sdinv[wid * 16 + g + 8] : g_dinv[r1];
    __half* Y = g_bufY;
    if (m0 < M) {
        __half* dst = Y + (size_t)m0 * N_DIM + tig * 2;
        #pragma unroll
        for (int nt = 0; nt < NT; nt++)
            *(__half2*)(dst + nt * 8) = __floats2half2_rn(dv0 * acc[nt][0], dv0 * acc[nt][1]);
    }
    if (m1 < M) {
        __half* dst = Y + (size_t)m1 * N_DIM + tig * 2;
        #pragma unroll
        for (int nt = 0; nt < NT; nt++)
            *(__half2*)(dst + nt * 8) = __floats2half2_rn(dv1 * acc[nt][2], dv1 * acc[nt][3]);
    }
}

// ---------------------------------------------------------------- SpMM (CSR)
// warp per node, F=128: lanes split 16x2 -> 2 edges per LDG.128.
__global__ __launch_bounds__(256) void agg_relu128_h(int n) {
    const __half* Y = g_bufY;
    __half* H = g_bufH;
    int warpId = (blockIdx.x * blockDim.x + threadIdx.x) >> 5;
    int lane = threadIdx.x & 31;
    if (warpId >= n) return;
    const int grp = lane >> 4;
    const int chunk = lane & 15;
    int s = g_rowstart[warpId];
    int e = g_rowstart[warpId + 1];
    float acc[8];
    #pragma unroll
    for (int j = 0; j < 8; j++) acc[j] = 0.f;

    int i = s;
    for (; i + 4 <= e; i += 4) {
        int ca = __ldg(g_col + i + grp);
        int cb = __ldg(g_col + i + 2 + grp);
        uint4 ra = __ldg((const uint4*)(Y + (size_t)ca * 128) + chunk);
        uint4 rb = __ldg((const uint4*)(Y + (size_t)cb * 128) + chunk);
        acc8(acc, ra);
        acc8(acc, rb);
    }
    for (; i + 2 <= e; i += 2) {
        int c = __ldg(g_col + i + grp);
        uint4 r = __ldg((const uint4*)(Y + (size_t)c * 128) + chunk);
        acc8(acc, r);
    }
    if (i < e && grp == 0) {
        int c = __ldg(g_col + i);
        uint4 r = __ldg((const uint4*)(Y + (size_t)c * 128) + chunk);
        acc8(acc, r);
    }
    #pragma unroll
    for (int j = 0; j < 8; j++)
        acc[j] += __shfl_xor_sync(0xffffffffu, acc[j], 16);

    float dv = g_dinv[warpId];
    if (grp == 0) {
        uint4 outp;
        outp.x = f2h2(fmaxf(dv * acc[0], 0.f), fmaxf(dv * acc[1], 0.f));
        outp.y = f2h2(fmaxf(dv * acc[2], 0.f), fmaxf(dv * acc[3], 0.f));
        outp.z = f2h2(fmaxf(dv * acc[4], 0.f), fmaxf(dv * acc[5], 0.f));
        outp.w = f2h2(fmaxf(dv * acc[6], 0.f), fmaxf(dv * acc[7], 0.f));
        ((uint4*)(H + (size_t)warpId * 128))[chunk] = outp;
    }
}

// warp per node, F=64: lanes split 8x4 -> 4 edges per LDG.128.
__global__ __launch_bounds__(256) void agg_softmax64_h(float* __restrict__ out, int n) {
    const __half* Y = g_bufY;
    int warpId = (blockIdx.x * blockDim.x + threadIdx.x) >> 5;
    int lane = threadIdx.x & 31;
    if (warpId >= n) return;
    const int sub = lane >> 3;
    const int chunk = lane & 7;
    int s = g_rowstart[warpId];
    int e = g_rowstart[warpId + 1];
    float acc[8];
    #pragma unroll
    for (int j = 0; j < 8; j++) acc[j] = 0.f;

    int i = s;
    for (; i + 4 <= e; i += 4) {
        int c = __ldg(g_col + i + sub);
        uint4 r = __ldg((const uint4*)(Y + (size_t)c * 64) + chunk);
        acc8(acc, r);
    }
    int rem = e - i;
    if (sub < rem) {
        int c = __ldg(g_col + i + sub);
        uint4 r = __ldg((const uint4*)(Y + (size_t)c * 64) + chunk);
        acc8(acc, r);
    }
    #pragma unroll
    for (int j = 0; j < 8; j++) {
        acc[j] += __shfl_xor_sync(0xffffffffu, acc[j], 8);
        acc[j] += __shfl_xor_sync(0xffffffffu, acc[j], 16);
    }

    float dv = g_dinv[warpId];
    #pragma unroll
    for (int j = 0; j < 8; j++) acc[j] = fmaxf(dv * acc[j], 0.f);

    float m = acc[0];
    #pragma unroll
    for (int j = 1; j < 8; j++) m = fmaxf(m, acc[j]);
    #pragma unroll
    for (int off = 4; off >= 1; off >>= 1)
        m = fmaxf(m, __shfl_xor_sync(0xffffffffu, m, off));
    float ssum = 0.f;
    #pragma unroll
    for (int j = 0; j < 8; j++) {
        acc[j] = __expf(acc[j] - m);
        ssum += acc[j];
    }
    #pragma unroll
    for (int off = 4; off >= 1; off >>= 1)
        ssum += __shfl_xor_sync(0xffffffffu, ssum, off);
    float inv = 1.0f / ssum;

    if (sub == 0) {
        float* dst = out + (size_t)warpId * 64 + chunk * 8;
        *(float4*)(dst + 0) = make_float4(acc[0] * inv, acc[1] * inv, acc[2] * inv, acc[3] * inv);
        *(float4*)(dst + 4) = make_float4(acc[4] * inv, acc[5] * inv, acc[6] * inv, acc[7] * inv);
    }
}

// ---------------------------------------------------------------- launch
extern "C" void kernel_launch(void* const* d_in, const int* in_sizes, int n_in,
                              void* d_out, int out_size) {
    const float* X = (const float*)d_in[0];
    const void* ei = d_in[1];
    const float* W1 = (const float*)d_in[2];
    const float* W2 = (const float*)d_in[3];
    const float* W3 = (const float*)d_in[4];
    float* out = (float*)d_out;

    const int N = in_sizes[0] / 128;   // 50000
    const int E = in_sizes[1] / 2;     // 800000

    const int T = 256;
    const int gemmBlocks = (N + 127) / 128;
    const int aggBlocks = (N * 32 + T - 1) / T;
    const int SMEM_128 = 32 * (128 + 4) * sizeof(uint2);  // 33792
    const int SMEM_64  = 32 * (64 + 4) * sizeof(uint2);   // 17408

    auto g1 = gemm_mma<128, 1, true>;
    auto g2 = gemm_mma<128, 2, false>;
    auto g3 = gemm_mma<64, 3, false>;

    prep_all_kernel<<<40, 256>>>(W1, W2, W3, ei, E, N);  // 1 (+dtype probe)
    count_deg_kernel<<<(E + T - 1) / T, T>>>(ei, E);     // 2 (+rank)
    scan_kernel<<<1, 1024>>>(N);                         // 3
    g1<<<gemmBlocks, 256, SMEM_128>>>(X, N);             // 4 (+dinv)
    scatter_kernel<<<(E + T - 1) / T, T>>>(ei, E);       // 5 (atomic-free)

    agg_relu128_h<<<aggBlocks, T>>>(N);                  // 6
    g2<<<gemmBlocks, 256, SMEM_128>>>(nullptr, N);       // 7
    agg_relu128_h<<<aggBlocks, T>>>(N);                  // 8
    g3<<<gemmBlocks, 256, SMEM_64>>>(nullptr, N);        // 9
    agg_softmax64_h<<<aggBlocks, T>>>(out, N);           // 10
}